// round 6
// baseline (speedup 1.0000x reference)
#include <cuda_runtime.h>
#include <cuda_bf16.h>
#include <cstdint>
#include <cstddef>

#define N_NODES 50000
#define N_EDGES 800000
#define BN_EPS  1e-5f

// ---------------- scratch (static device globals; allocation-free) ----------
__device__ __nv_bfloat16 g_xhi[(size_t)N_NODES * 256];
__device__ __nv_bfloat16 g_xlo[(size_t)N_NODES * 256];
__device__ __nv_bfloat16 g_w0hi[128 * 256], g_w0lo[128 * 256];
__device__ __nv_bfloat16 g_w1hi[128 * 256], g_w1lo[128 * 256];
__device__ __nv_bfloat16 g_w2hi[32 * 256],  g_w2lo[32 * 256];
__device__ float g_proj[(size_t)N_NODES * 128];
__device__ float g_pre [(size_t)N_NODES * 128];
__device__ float g_stats[512];                 // layer0: [0:256), layer1: [256:512)
__device__ int   g_deg[N_NODES];
__device__ int   g_cur[N_NODES];
__device__ int   g_off[N_NODES + 1];
__device__ int2  g_erec[N_EDGES];              // (src, w bits), grouped by dst

// ---------------- asm helpers ------------------------------------------------
__device__ __forceinline__ void mma16816(float* d, const uint32_t* a, const uint32_t* b) {
    asm volatile(
        "mma.sync.aligned.m16n8k16.row.col.f32.bf16.bf16.f32 "
        "{%0,%1,%2,%3}, {%4,%5,%6,%7}, {%8,%9}, {%0,%1,%2,%3};"
        : "+f"(d[0]), "+f"(d[1]), "+f"(d[2]), "+f"(d[3])
        : "r"(a[0]), "r"(a[1]), "r"(a[2]), "r"(a[3]), "r"(b[0]), "r"(b[1]));
}
__device__ __forceinline__ void ldsm4(uint32_t* r, uint32_t a) {
    asm volatile("ldmatrix.sync.aligned.m8n8.x4.shared.b16 {%0,%1,%2,%3}, [%4];"
                 : "=r"(r[0]), "=r"(r[1]), "=r"(r[2]), "=r"(r[3]) : "r"(a));
}
__device__ __forceinline__ uint32_t smem_u32(const void* p) {
    uint32_t a;
    asm("{ .reg .u64 t; cvta.to.shared.u64 t, %1; cvt.u32.u64 %0, t; }" : "=r"(a) : "l"(p));
    return a;
}
__device__ __forceinline__ void cpasync16(uint32_t dst, const void* src, int src_sz) {
    asm volatile("cp.async.ca.shared.global [%0], [%1], 16, %2;"
                 :: "r"(dst), "l"(src), "r"(src_sz));
}
#define CP_COMMIT() asm volatile("cp.async.commit_group;" ::: "memory")
__device__ __forceinline__ void redg_v4(float* p, float4 v) {
    asm volatile("red.global.add.v4.f32 [%0], {%1,%2,%3,%4};"
                 :: "l"(p), "f"(v.x), "f"(v.y), "f"(v.z), "f"(v.w) : "memory");
}

// ---------------- CSR build ---------------------------------------------------
__global__ __launch_bounds__(256)
void csr_zero(int* __restrict__ deg, float* __restrict__ stats) {
    int i = blockIdx.x * blockDim.x + threadIdx.x;
    if (i < N_NODES) deg[i] = 0;
    if (i < 512) stats[i] = 0.0f;
}
__global__ __launch_bounds__(256)
void csr_hist(const int* __restrict__ dst, int* __restrict__ deg) {
    int e = blockIdx.x * blockDim.x + threadIdx.x;
    if (e < N_EDGES) atomicAdd(&deg[dst[e]], 1);
}
__global__ __launch_bounds__(1024)
void csr_scan(const int* __restrict__ deg, int* __restrict__ off, int* __restrict__ cur) {
    __shared__ int wsum[32];
    const int t = threadIdx.x;
    const int base = t * 49;
    int s = 0;
#pragma unroll 7
    for (int k = 0; k < 49; k++) {
        int idx = base + k;
        if (idx < N_NODES) s += deg[idx];
    }
    int v = s;
#pragma unroll
    for (int o = 1; o < 32; o <<= 1) {
        int u = __shfl_up_sync(0xFFFFFFFFu, v, o);
        if ((t & 31) >= o) v += u;
    }
    if ((t & 31) == 31) wsum[t >> 5] = v;
    __syncthreads();
    if (t < 32) {
        int w = wsum[t];
#pragma unroll
        for (int o = 1; o < 32; o <<= 1) {
            int u = __shfl_up_sync(0xFFFFFFFFu, w, o);
            if (t >= o) w += u;
        }
        wsum[t] = w;
    }
    __syncthreads();
    int run = v - s + ((t >= 32) ? wsum[(t >> 5) - 1] : 0);
#pragma unroll 7
    for (int k = 0; k < 49; k++) {
        int idx = base + k;
        if (idx < N_NODES) {
            off[idx] = run;
            cur[idx] = run;
            run += deg[idx];
        }
    }
    if (t == 1023) off[N_NODES] = run;
}
__global__ __launch_bounds__(256)
void csr_fill(const int* __restrict__ src, const int* __restrict__ dst,
              const float* __restrict__ w, int* __restrict__ cur, int2* __restrict__ erec) {
    int e = blockIdx.x * blockDim.x + threadIdx.x;
    if (e >= N_EDGES) return;
    int pos = atomicAdd(&cur[dst[e]], 1);
    erec[pos] = make_int2(src[e], __float_as_int(w[e]));
}

// ---------------- fused CSR aggregation + BN stats (width 128) -----------------
// Grid-strided: warp per node. Also accumulates column sum/sumsq into stats.
__global__ __launch_bounds__(256)
void agg128_stats(const float* __restrict__ h, const int* __restrict__ off,
                  const int2* __restrict__ erec, float* __restrict__ out,
                  float* __restrict__ stats) {
    const int warp = threadIdx.x >> 5;
    const int lane = threadIdx.x & 31;
    const float4* h4 = (const float4*)h;
    float4 S = make_float4(0.f, 0.f, 0.f, 0.f);
    float4 Q = make_float4(0.f, 0.f, 0.f, 0.f);

    for (int n = blockIdx.x * 8 + warp; n < N_NODES; n += gridDim.x * 8) {
        int i = off[n], end = off[n + 1];
        float4 acc = make_float4(0.f, 0.f, 0.f, 0.f);
        for (; i + 1 < end; i += 2) {
            int2 r0 = erec[i], r1 = erec[i + 1];
            float w0 = __int_as_float(r0.y), w1 = __int_as_float(r1.y);
            float4 v0 = h4[(size_t)r0.x * 32 + lane];
            float4 v1 = h4[(size_t)r1.x * 32 + lane];
            acc.x += w0 * v0.x + w1 * v1.x;
            acc.y += w0 * v0.y + w1 * v1.y;
            acc.z += w0 * v0.z + w1 * v1.z;
            acc.w += w0 * v0.w + w1 * v1.w;
        }
        if (i < end) {
            int2 r0 = erec[i];
            float w0 = __int_as_float(r0.y);
            float4 v0 = h4[(size_t)r0.x * 32 + lane];
            acc.x += w0 * v0.x; acc.y += w0 * v0.y;
            acc.z += w0 * v0.z; acc.w += w0 * v0.w;
        }
        ((float4*)out)[(size_t)n * 32 + lane] = acc;
        S.x += acc.x; S.y += acc.y; S.z += acc.z; S.w += acc.w;
        Q.x += acc.x * acc.x; Q.y += acc.y * acc.y;
        Q.z += acc.z * acc.z; Q.w += acc.w * acc.w;
    }

    __shared__ float4 sS[8][32], sQ[8][32];
    sS[warp][lane] = S;
    sQ[warp][lane] = Q;
    __syncthreads();
    if (warp == 0) {
        float4 TS = sS[0][lane], TQ = sQ[0][lane];
#pragma unroll
        for (int g = 1; g < 8; g++) {
            float4 a = sS[g][lane], b = sQ[g][lane];
            TS.x += a.x; TS.y += a.y; TS.z += a.z; TS.w += a.w;
            TQ.x += b.x; TQ.y += b.y; TQ.z += b.z; TQ.w += b.w;
        }
        redg_v4(stats + lane * 4, TS);
        redg_v4(stats + 128 + lane * 4, TQ);
    }
}

// width 32: 8 lanes per node
__global__ __launch_bounds__(256)
void agg_csr32(const float* __restrict__ h, const int* __restrict__ off,
               const int2* __restrict__ erec, float* __restrict__ out) {
    int gid = blockIdx.x * blockDim.x + threadIdx.x;
    int n = gid >> 3;
    int sl = gid & 7;
    if (n >= N_NODES) return;
    int i = off[n], end = off[n + 1];
    const float4* h4 = (const float4*)h;
    float4 acc = make_float4(0.f, 0.f, 0.f, 0.f);
    for (; i + 1 < end; i += 2) {
        int2 r0 = erec[i], r1 = erec[i + 1];
        float w0 = __int_as_float(r0.y), w1 = __int_as_float(r1.y);
        float4 v0 = h4[(size_t)r0.x * 8 + sl];
        float4 v1 = h4[(size_t)r1.x * 8 + sl];
        acc.x += w0 * v0.x + w1 * v1.x;
        acc.y += w0 * v0.y + w1 * v1.y;
        acc.z += w0 * v0.z + w1 * v1.z;
        acc.w += w0 * v0.w + w1 * v1.w;
    }
    if (i < end) {
        int2 r0 = erec[i];
        float w0 = __int_as_float(r0.y);
        float4 v0 = h4[(size_t)r0.x * 8 + sl];
        acc.x += w0 * v0.x; acc.y += w0 * v0.y;
        acc.z += w0 * v0.z; acc.w += w0 * v0.w;
    }
    ((float4*)out)[(size_t)n * 8 + sl] = acc;
}

// ---------------- conversion kernels -------------------------------------------
__global__ __launch_bounds__(256)
void convert_x4(const float* __restrict__ x, __nv_bfloat16* __restrict__ hi,
                __nv_bfloat16* __restrict__ lo, int n4) {
    int i = blockIdx.x * blockDim.x + threadIdx.x;
    if (i >= n4) return;
    float4 v = ((const float4*)x)[i];
    __nv_bfloat16 h0 = __float2bfloat16(v.x), h1 = __float2bfloat16(v.y);
    __nv_bfloat16 h2 = __float2bfloat16(v.z), h3 = __float2bfloat16(v.w);
    __nv_bfloat162 a = {h0, h1}, b = {h2, h3};
    ((uint2*)hi)[i] = make_uint2(*(uint32_t*)&a, *(uint32_t*)&b);
    __nv_bfloat162 c = {__float2bfloat16(v.x - __bfloat162float(h0)),
                        __float2bfloat16(v.y - __bfloat162float(h1))};
    __nv_bfloat162 d = {__float2bfloat16(v.z - __bfloat162float(h2)),
                        __float2bfloat16(v.w - __bfloat162float(h3))};
    ((uint2*)lo)[i] = make_uint2(*(uint32_t*)&c, *(uint32_t*)&d);
}

// All 3 weight matrices in one launch. W [K=256, N] -> Wt hi/lo [N, 256].
__global__ __launch_bounds__(256)
void convert_w_all(const float* __restrict__ W0, const float* __restrict__ W1,
                   const float* __restrict__ W2,
                   __nv_bfloat16* __restrict__ w0hi, __nv_bfloat16* __restrict__ w0lo,
                   __nv_bfloat16* __restrict__ w1hi, __nv_bfloat16* __restrict__ w1lo,
                   __nv_bfloat16* __restrict__ w2hi, __nv_bfloat16* __restrict__ w2lo) {
    int i = blockIdx.x * blockDim.x + threadIdx.x;   // 0 .. 288*256-1
    const float* W; __nv_bfloat16 *hi, *lo; int N, base;
    if (i < 128 * 256)      { W = W0; hi = w0hi; lo = w0lo; N = 128; base = 0; }
    else if (i < 256 * 256) { W = W1; hi = w1hi; lo = w1lo; N = 128; base = 128 * 256; }
    else if (i < 288 * 256) { W = W2; hi = w2hi; lo = w2lo; N = 32;  base = 256 * 256; }
    else return;
    int li = i - base;
    int n = li >> 8, k = li & 255;
    float v = W[(size_t)k * N + n];
    __nv_bfloat16 h = __float2bfloat16(v);
    hi[li] = h;
    lo[li] = __float2bfloat16(v - __bfloat162float(h));
}

// ---------------- pipelined ldmatrix GEMM --------------------------------------
// C[M,NT] = A[M,256] @ Wt[NT,256]^T. CTA 128xNT, 8 warps (4m x 2n), BK=32.
// smem row stride 80B: conflict-free for ldmatrix.
template <int NT>
__device__ __forceinline__ void gload(uint32_t sbase, const uint4* Ahi4, const uint4* Alo4,
                                      const uint4* Bhi4, const uint4* Blo4,
                                      int m0, int M, int ch, int tid) {
    const uint32_t sAhi = sbase;
    const uint32_t sAlo = sbase + 128 * 80;
    const uint32_t sBhi = sbase + 256 * 80;
    const uint32_t sBlo = sbase + 256 * 80 + NT * 80;
#pragma unroll
    for (int j = 0; j < 2; j++) {
        int i   = tid + j * 256;
        int row = i >> 2, c4 = i & 3;
        int gr  = m0 + row;
        int ok  = (gr < M) ? 16 : 0;
        size_t g = (size_t)(ok ? gr : 0) * 32 + ch * 4 + c4;
        cpasync16(sAhi + row * 80 + c4 * 16, Ahi4 + g, ok);
        cpasync16(sAlo + row * 80 + c4 * 16, Alo4 + g, ok);
    }
#pragma unroll
    for (int j = 0; j < (NT * 4 + 255) / 256; j++) {
        int i = tid + j * 256;
        if (i < NT * 4) {
            int row = i >> 2, c4 = i & 3;
            size_t g = (size_t)row * 32 + ch * 4 + c4;
            cpasync16(sBhi + row * 80 + c4 * 16, Bhi4 + g, 16);
            cpasync16(sBlo + row * 80 + c4 * 16, Blo4 + g, 16);
        }
    }
}

template <int NT>
__global__ __launch_bounds__(256, 2)
void gemm_mma3(const __nv_bfloat16* __restrict__ Ahi, const __nv_bfloat16* __restrict__ Alo,
               const __nv_bfloat16* __restrict__ Bhi, const __nv_bfloat16* __restrict__ Blo,
               float* __restrict__ C, int M) {
    constexpr int WNT   = NT / 16;
    constexpr int STAGE = (256 + 2 * NT) * 80;
    extern __shared__ char sm[];
    const uint32_t smu = smem_u32(sm);

    const int tid  = threadIdx.x;
    const int wid  = tid >> 5;
    const int lane = tid & 31;
    const int wm   = wid & 3;
    const int wn   = wid >> 2;
    const int m0   = blockIdx.x * 128;
    const int r    = lane >> 2;
    const int c2   = (lane & 3) * 2;

    const uint32_t aOff = (uint32_t)(lane & 15) * 80 + ((lane & 16) ? 16u : 0u);
    const uint32_t bOff = (uint32_t)((lane & 7) + ((lane & 16) ? 8 : 0)) * 80 +
                          ((lane & 8) ? 16u : 0u);

    const uint4* Ahi4 = (const uint4*)Ahi;
    const uint4* Alo4 = (const uint4*)Alo;
    const uint4* Bhi4 = (const uint4*)Bhi;
    const uint4* Blo4 = (const uint4*)Blo;

    float acc[2][WNT][4];
#pragma unroll
    for (int mt = 0; mt < 2; mt++)
#pragma unroll
        for (int j = 0; j < WNT; j++)
#pragma unroll
            for (int q = 0; q < 4; q++) acc[mt][j][q] = 0.0f;

    gload<NT>(smu, Ahi4, Alo4, Bhi4, Blo4, m0, M, 0, tid);
    CP_COMMIT();

    for (int ch = 0; ch < 8; ch++) {
        if (ch < 7) {
            gload<NT>(smu + ((ch + 1) & 1) * STAGE, Ahi4, Alo4, Bhi4, Blo4, m0, M, ch + 1, tid);
            CP_COMMIT();
            asm volatile("cp.async.wait_group 1;" ::: "memory");
        } else {
            asm volatile("cp.async.wait_group 0;" ::: "memory");
        }
        __syncthreads();

        const uint32_t st = smu + (ch & 1) * STAGE;

#pragma unroll
        for (int ks = 0; ks < 2; ks++) {
            const uint32_t k0b = ks * 32;
            uint32_t ah[2][4], al[2][4];
#pragma unroll
            for (int mt = 0; mt < 2; mt++) {
                uint32_t rowb = (uint32_t)(wm * 32 + mt * 16) * 80;
                ldsm4(ah[mt], st + rowb + aOff + k0b);
                ldsm4(al[mt], st + 128 * 80 + rowb + aOff + k0b);
            }
#pragma unroll
            for (int p = 0; p < WNT / 2; p++) {
                uint32_t n0b = (uint32_t)(wn * (NT / 2) + p * 16) * 80;
                uint32_t ba = st + 256 * 80 + n0b + bOff + k0b;
                uint32_t bh4[4], bl4[4];
                ldsm4(bh4, ba);
                ldsm4(bl4, ba + NT * 80);
#pragma unroll
                for (int jj = 0; jj < 2; jj++) {
                    int j = p * 2 + jj;
#pragma unroll
                    for (int mt = 0; mt < 2; mt++) {
                        mma16816(acc[mt][j], ah[mt], bh4 + jj * 2);
                        mma16816(acc[mt][j], ah[mt], bl4 + jj * 2);
                        mma16816(acc[mt][j], al[mt], bh4 + jj * 2);
                    }
                }
            }
        }
        __syncthreads();
    }

#pragma unroll
    for (int mt = 0; mt < 2; mt++) {
        int row0 = m0 + wm * 32 + mt * 16 + r;
#pragma unroll
        for (int j = 0; j < WNT; j++) {
            int col = wn * (NT / 2) + j * 8 + c2;
            if (row0 < M)
                *(float2*)&C[(size_t)row0 * NT + col] = make_float2(acc[mt][j][0], acc[mt][j][1]);
            if (row0 + 8 < M)
                *(float2*)&C[(size_t)(row0 + 8) * NT + col] = make_float2(acc[mt][j][2], acc[mt][j][3]);
        }
    }
}

// ---------------- BN apply + ReLU + concat -> bf16 hi/lo ------------------------
__global__ __launch_bounds__(256)
void bn_apply_concat4(const float* __restrict__ pre, const float* __restrict__ stats,
                      const float* __restrict__ gamma, const float* __restrict__ beta,
                      __nv_bfloat16* __restrict__ xhi, __nv_bfloat16* __restrict__ xlo) {
    int idx4 = blockIdx.x * blockDim.x + threadIdx.x;
    if (idx4 >= N_NODES * 32) return;
    int r = idx4 >> 5;
    int c = (idx4 & 31) * 4;
    const float invN = 1.0f / (float)N_NODES;
    float4 v = *(const float4*)(pre + (size_t)r * 128 + c);
    float vv[4] = {v.x, v.y, v.z, v.w};
    float hv[4];
#pragma unroll
    for (int qd = 0; qd < 4; qd++) {
        float mu  = stats[c + qd] * invN;
        float var = stats[128 + c + qd] * invN - mu * mu;
        float inv = rsqrtf(var + BN_EPS);
        float bn  = (vv[qd] - mu) * inv * gamma[c + qd] + beta[c + qd];
        hv[qd] = bn > 0.0f ? bn : 0.0f;
    }
    size_t o0 = (size_t)r * 256 + c;
    {
        __nv_bfloat16 h0 = __float2bfloat16(hv[0]), h1 = __float2bfloat16(hv[1]);
        __nv_bfloat16 h2 = __float2bfloat16(hv[2]), h3 = __float2bfloat16(hv[3]);
        __nv_bfloat162 a = {h0, h1}, b = {h2, h3};
        *(uint2*)(xhi + o0) = make_uint2(*(uint32_t*)&a, *(uint32_t*)&b);
        __nv_bfloat162 la = {__float2bfloat16(hv[0] - __bfloat162float(h0)),
                             __float2bfloat16(hv[1] - __bfloat162float(h1))};
        __nv_bfloat162 lb = {__float2bfloat16(hv[2] - __bfloat162float(h2)),
                             __float2bfloat16(hv[3] - __bfloat162float(h3))};
        *(uint2*)(xlo + o0) = make_uint2(*(uint32_t*)&la, *(uint32_t*)&lb);
    }
    {
        __nv_bfloat16 h0 = __float2bfloat16(vv[0]), h1 = __float2bfloat16(vv[1]);
        __nv_bfloat16 h2 = __float2bfloat16(vv[2]), h3 = __float2bfloat16(vv[3]);
        __nv_bfloat162 a = {h0, h1}, b = {h2, h3};
        *(uint2*)(xhi + o0 + 128) = make_uint2(*(uint32_t*)&a, *(uint32_t*)&b);
        __nv_bfloat162 la = {__float2bfloat16(vv[0] - __bfloat162float(h0)),
                             __float2bfloat16(vv[1] - __bfloat162float(h1))};
        __nv_bfloat162 lb = {__float2bfloat16(vv[2] - __bfloat162float(h2)),
                             __float2bfloat16(vv[3] - __bfloat162float(h3))};
        *(uint2*)(xlo + o0 + 128) = make_uint2(*(uint32_t*)&la, *(uint32_t*)&lb);
    }
}

// ---------------- launch ---------------------------------------------------------
extern "C" void kernel_launch(void* const* d_in, const int* in_sizes, int n_in,
                              void* d_out, int out_size) {
    const float* x      = (const float*)d_in[0];
    const int*   src    = (const int*)  d_in[1];
    const int*   dst    = (const int*)  d_in[2];
    const float* ew     = (const float*)d_in[3];
    const float* W0     = (const float*)d_in[4];
    const float* W1     = (const float*)d_in[5];
    const float* W2     = (const float*)d_in[6];
    const float* gamma0 = (const float*)d_in[7];
    const float* beta0  = (const float*)d_in[8];
    const float* gamma1 = (const float*)d_in[9];
    const float* beta1  = (const float*)d_in[10];
    float* out = (float*)d_out;

    __nv_bfloat16 *xhi, *xlo, *w0hi, *w0lo, *w1hi, *w1lo, *w2hi, *w2lo;
    float *proj, *pre, *stats;
    int *deg, *cur, *off;
    int2 *erec;
    cudaGetSymbolAddress((void**)&xhi,   g_xhi);
    cudaGetSymbolAddress((void**)&xlo,   g_xlo);
    cudaGetSymbolAddress((void**)&w0hi,  g_w0hi);
    cudaGetSymbolAddress((void**)&w0lo,  g_w0lo);
    cudaGetSymbolAddress((void**)&w1hi,  g_w1hi);
    cudaGetSymbolAddress((void**)&w1lo,  g_w1lo);
    cudaGetSymbolAddress((void**)&w2hi,  g_w2hi);
    cudaGetSymbolAddress((void**)&w2lo,  g_w2lo);
    cudaGetSymbolAddress((void**)&proj,  g_proj);
    cudaGetSymbolAddress((void**)&pre,   g_pre);
    cudaGetSymbolAddress((void**)&stats, g_stats);
    cudaGetSymbolAddress((void**)&deg,   g_deg);
    cudaGetSymbolAddress((void**)&cur,   g_cur);
    cudaGetSymbolAddress((void**)&off,   g_off);
    cudaGetSymbolAddress((void**)&erec,  g_erec);

    const int smem128 = 2 * (256 + 2 * 128) * 80;   // 81920
    const int smem32  = 2 * (256 + 2 * 32)  * 80;   // 51200
    cudaFuncSetAttribute(gemm_mma3<128>, cudaFuncAttributeMaxDynamicSharedMemorySize, smem128);
    cudaFuncSetAttribute(gemm_mma3<32>,  cudaFuncAttributeMaxDynamicSharedMemorySize, smem32);

    const int nX4      = N_NODES * 256 / 4;
    const int bnBlocks = (N_NODES * 32 + 255) / 256;
    const int mTiles   = (N_NODES + 127) / 128;     // 391
    const int edgeB    = (N_EDGES + 255) / 256;      // 3125
    const int aggB32   = (N_NODES * 8 + 255) / 256;  // 1563

    // ---- CSR build + conversions (shared by all layers) ----
    csr_zero<<<(N_NODES + 255) / 256, 256>>>(deg, stats);
    csr_hist<<<edgeB, 256>>>(dst, deg);
    csr_scan<<<1, 1024>>>(deg, off, cur);
    csr_fill<<<edgeB, 256>>>(src, dst, ew, cur, erec);
    convert_x4<<<(nX4 + 255) / 256, 256>>>(x, xhi, xlo, nX4);
    convert_w_all<<<(288 * 256 + 255) / 256, 256>>>(W0, W1, W2, w0hi, w0lo,
                                                    w1hi, w1lo, w2hi, w2lo);

    // ---- layer 0 ----
    gemm_mma3<128><<<mTiles, 256, smem128>>>(xhi, xlo, w0hi, w0lo, proj, N_NODES);
    agg128_stats<<<512, 256>>>(proj, off, erec, pre, stats);
    bn_apply_concat4<<<bnBlocks, 256>>>(pre, stats, gamma0, beta0, xhi, xlo);

    // ---- layer 1 ----
    gemm_mma3<128><<<mTiles, 256, smem128>>>(xhi, xlo, w1hi, w1lo, proj, N_NODES);
    agg128_stats<<<512, 256>>>(proj, off, erec, pre, stats + 256);
    bn_apply_concat4<<<bnBlocks, 256>>>(pre, stats + 256, gamma1, beta1, xhi, xlo);

    // ---- output layer (N=32) ----
    gemm_mma3<32><<<mTiles, 256, smem32>>>(xhi, xlo, w2hi, w2lo, proj, N_NODES);
    agg_csr32<<<aggB32, 256>>>(proj, off, erec, out);
}

// round 7
// speedup vs baseline: 1.1468x; 1.1468x over previous
#include <cuda_runtime.h>
#include <cuda_bf16.h>
#include <cstdint>
#include <cstddef>

#define N_NODES 50000
#define N_EDGES 800000
#define BN_EPS  1e-5f

// ---------------- scratch (static device globals; allocation-free) ----------
__device__ __nv_bfloat16 g_xhi[(size_t)N_NODES * 256];
__device__ __nv_bfloat16 g_xlo[(size_t)N_NODES * 256];
__device__ __nv_bfloat16 g_w0hi[128 * 256], g_w0lo[128 * 256];
__device__ __nv_bfloat16 g_w1hi[128 * 256], g_w1lo[128 * 256];
__device__ __nv_bfloat16 g_w2hi[32 * 256],  g_w2lo[32 * 256];
__device__ float g_proj[(size_t)N_NODES * 128];
__device__ float g_pre [(size_t)N_NODES * 128];
__device__ float g_stats[512];                 // layer0: [0:256), layer1: [256:512)
__device__ int   g_deg[N_NODES];
__device__ int   g_cur[N_NODES];
__device__ int   g_off[N_NODES + 1];
__device__ int2  g_erec[N_EDGES];              // (src, w bits), grouped by dst

// ---------------- asm helpers ------------------------------------------------
__device__ __forceinline__ void mma16816(float* d, const uint32_t* a, const uint32_t* b) {
    asm volatile(
        "mma.sync.aligned.m16n8k16.row.col.f32.bf16.bf16.f32 "
        "{%0,%1,%2,%3}, {%4,%5,%6,%7}, {%8,%9}, {%0,%1,%2,%3};"
        : "+f"(d[0]), "+f"(d[1]), "+f"(d[2]), "+f"(d[3])
        : "r"(a[0]), "r"(a[1]), "r"(a[2]), "r"(a[3]), "r"(b[0]), "r"(b[1]));
}
__device__ __forceinline__ void ldsm4(uint32_t* r, uint32_t a) {
    asm volatile("ldmatrix.sync.aligned.m8n8.x4.shared.b16 {%0,%1,%2,%3}, [%4];"
                 : "=r"(r[0]), "=r"(r[1]), "=r"(r[2]), "=r"(r[3]) : "r"(a));
}
__device__ __forceinline__ uint32_t smem_u32(const void* p) {
    uint32_t a;
    asm("{ .reg .u64 t; cvta.to.shared.u64 t, %1; cvt.u32.u64 %0, t; }" : "=r"(a) : "l"(p));
    return a;
}
__device__ __forceinline__ void cpasync16(uint32_t dst, const void* src, int src_sz) {
    asm volatile("cp.async.ca.shared.global [%0], [%1], 16, %2;"
                 :: "r"(dst), "l"(src), "r"(src_sz));
}
#define CP_COMMIT() asm volatile("cp.async.commit_group;" ::: "memory")
__device__ __forceinline__ void redg_v4(float* p, float4 v) {
    asm volatile("red.global.add.v4.f32 [%0], {%1,%2,%3,%4};"
                 :: "l"(p), "f"(v.x), "f"(v.y), "f"(v.z), "f"(v.w) : "memory");
}

// ---------------- CSR build ---------------------------------------------------
__global__ __launch_bounds__(256)
void csr_zero(int* __restrict__ deg, float* __restrict__ stats) {
    int i = blockIdx.x * blockDim.x + threadIdx.x;
    if (i < N_NODES) deg[i] = 0;
    if (i < 512) stats[i] = 0.0f;
}
// 4 edges per thread for MLP
__global__ __launch_bounds__(256)
void csr_hist(const int* __restrict__ dst, int* __restrict__ deg) {
    int b = (blockIdx.x * blockDim.x + threadIdx.x) * 4;
    if (b + 3 < N_EDGES) {
        int4 d = *(const int4*)(dst + b);
        atomicAdd(&deg[d.x], 1);
        atomicAdd(&deg[d.y], 1);
        atomicAdd(&deg[d.z], 1);
        atomicAdd(&deg[d.w], 1);
    } else {
        for (int e = b; e < N_EDGES; e++) atomicAdd(&deg[dst[e]], 1);
    }
}
__global__ __launch_bounds__(1024)
void csr_scan(const int* __restrict__ deg, int* __restrict__ off, int* __restrict__ cur) {
    __shared__ int wsum[32];
    const int t = threadIdx.x;
    const int base = t * 49;
    int s = 0;
#pragma unroll 7
    for (int k = 0; k < 49; k++) {
        int idx = base + k;
        if (idx < N_NODES) s += deg[idx];
    }
    int v = s;
#pragma unroll
    for (int o = 1; o < 32; o <<= 1) {
        int u = __shfl_up_sync(0xFFFFFFFFu, v, o);
        if ((t & 31) >= o) v += u;
    }
    if ((t & 31) == 31) wsum[t >> 5] = v;
    __syncthreads();
    if (t < 32) {
        int w = wsum[t];
#pragma unroll
        for (int o = 1; o < 32; o <<= 1) {
            int u = __shfl_up_sync(0xFFFFFFFFu, w, o);
            if (t >= o) w += u;
        }
        wsum[t] = w;
    }
    __syncthreads();
    int run = v - s + ((t >= 32) ? wsum[(t >> 5) - 1] : 0);
#pragma unroll 7
    for (int k = 0; k < 49; k++) {
        int idx = base + k;
        if (idx < N_NODES) {
            off[idx] = run;
            cur[idx] = run;
            run += deg[idx];
        }
    }
    if (t == 1023) off[N_NODES] = run;
}
// 4 edges per thread for MLP
__global__ __launch_bounds__(256)
void csr_fill(const int* __restrict__ src, const int* __restrict__ dst,
              const float* __restrict__ w, int* __restrict__ cur, int2* __restrict__ erec) {
    int b = (blockIdx.x * blockDim.x + threadIdx.x) * 4;
    if (b + 3 < N_EDGES) {
        int4   s = *(const int4*)(src + b);
        int4   d = *(const int4*)(dst + b);
        float4 v = *(const float4*)(w + b);
        int p0 = atomicAdd(&cur[d.x], 1);
        int p1 = atomicAdd(&cur[d.y], 1);
        int p2 = atomicAdd(&cur[d.z], 1);
        int p3 = atomicAdd(&cur[d.w], 1);
        erec[p0] = make_int2(s.x, __float_as_int(v.x));
        erec[p1] = make_int2(s.y, __float_as_int(v.y));
        erec[p2] = make_int2(s.z, __float_as_int(v.z));
        erec[p3] = make_int2(s.w, __float_as_int(v.w));
    } else {
        for (int e = b; e < N_EDGES; e++) {
            int pos = atomicAdd(&cur[dst[e]], 1);
            erec[pos] = make_int2(src[e], __float_as_int(w[e]));
        }
    }
}

// ---------------- fused CSR aggregation + BN stats (width 128) -----------------
// Grid-strided at full occupancy (1184 blocks = 148 SMs x 8 CTAs).
__global__ __launch_bounds__(256)
void agg128_stats(const float* __restrict__ h, const int* __restrict__ off,
                  const int2* __restrict__ erec, float* __restrict__ out,
                  float* __restrict__ stats) {
    const int warp = threadIdx.x >> 5;
    const int lane = threadIdx.x & 31;
    const float4* h4 = (const float4*)h;
    float4 S = make_float4(0.f, 0.f, 0.f, 0.f);
    float4 Q = make_float4(0.f, 0.f, 0.f, 0.f);

    for (int n = blockIdx.x * 8 + warp; n < N_NODES; n += gridDim.x * 8) {
        int i = off[n], end = off[n + 1];
        float4 acc = make_float4(0.f, 0.f, 0.f, 0.f);
        for (; i + 1 < end; i += 2) {
            int2 r0 = erec[i], r1 = erec[i + 1];
            float w0 = __int_as_float(r0.y), w1 = __int_as_float(r1.y);
            float4 v0 = h4[(size_t)r0.x * 32 + lane];
            float4 v1 = h4[(size_t)r1.x * 32 + lane];
            acc.x += w0 * v0.x + w1 * v1.x;
            acc.y += w0 * v0.y + w1 * v1.y;
            acc.z += w0 * v0.z + w1 * v1.z;
            acc.w += w0 * v0.w + w1 * v1.w;
        }
        if (i < end) {
            int2 r0 = erec[i];
            float w0 = __int_as_float(r0.y);
            float4 v0 = h4[(size_t)r0.x * 32 + lane];
            acc.x += w0 * v0.x; acc.y += w0 * v0.y;
            acc.z += w0 * v0.z; acc.w += w0 * v0.w;
        }
        ((float4*)out)[(size_t)n * 32 + lane] = acc;
        S.x += acc.x; S.y += acc.y; S.z += acc.z; S.w += acc.w;
        Q.x += acc.x * acc.x; Q.y += acc.y * acc.y;
        Q.z += acc.z * acc.z; Q.w += acc.w * acc.w;
    }

    __shared__ float4 sS[8][32], sQ[8][32];
    sS[warp][lane] = S;
    sQ[warp][lane] = Q;
    __syncthreads();
    if (warp == 0) {
        float4 TS = sS[0][lane], TQ = sQ[0][lane];
#pragma unroll
        for (int g = 1; g < 8; g++) {
            float4 a = sS[g][lane], b = sQ[g][lane];
            TS.x += a.x; TS.y += a.y; TS.z += a.z; TS.w += a.w;
            TQ.x += b.x; TQ.y += b.y; TQ.z += b.z; TQ.w += b.w;
        }
        redg_v4(stats + lane * 4, TS);
        redg_v4(stats + 128 + lane * 4, TQ);
    }
}

// width 32: 8 lanes per node
__global__ __launch_bounds__(256)
void agg_csr32(const float* __restrict__ h, const int* __restrict__ off,
               const int2* __restrict__ erec, float* __restrict__ out) {
    int gid = blockIdx.x * blockDim.x + threadIdx.x;
    int n = gid >> 3;
    int sl = gid & 7;
    if (n >= N_NODES) return;
    int i = off[n], end = off[n + 1];
    const float4* h4 = (const float4*)h;
    float4 acc = make_float4(0.f, 0.f, 0.f, 0.f);
    for (; i + 1 < end; i += 2) {
        int2 r0 = erec[i], r1 = erec[i + 1];
        float w0 = __int_as_float(r0.y), w1 = __int_as_float(r1.y);
        float4 v0 = h4[(size_t)r0.x * 8 + sl];
        float4 v1 = h4[(size_t)r1.x * 8 + sl];
        acc.x += w0 * v0.x + w1 * v1.x;
        acc.y += w0 * v0.y + w1 * v1.y;
        acc.z += w0 * v0.z + w1 * v1.z;
        acc.w += w0 * v0.w + w1 * v1.w;
    }
    if (i < end) {
        int2 r0 = erec[i];
        float w0 = __int_as_float(r0.y);
        float4 v0 = h4[(size_t)r0.x * 8 + sl];
        acc.x += w0 * v0.x; acc.y += w0 * v0.y;
        acc.z += w0 * v0.z; acc.w += w0 * v0.w;
    }
    ((float4*)out)[(size_t)n * 8 + sl] = acc;
}

// ---------------- conversion kernels -------------------------------------------
__global__ __launch_bounds__(256)
void convert_x4(const float* __restrict__ x, __nv_bfloat16* __restrict__ hi,
                __nv_bfloat16* __restrict__ lo, int n4) {
    int i = blockIdx.x * blockDim.x + threadIdx.x;
    if (i >= n4) return;
    float4 v = ((const float4*)x)[i];
    __nv_bfloat16 h0 = __float2bfloat16(v.x), h1 = __float2bfloat16(v.y);
    __nv_bfloat16 h2 = __float2bfloat16(v.z), h3 = __float2bfloat16(v.w);
    __nv_bfloat162 a = {h0, h1}, b = {h2, h3};
    ((uint2*)hi)[i] = make_uint2(*(uint32_t*)&a, *(uint32_t*)&b);
    __nv_bfloat162 c = {__float2bfloat16(v.x - __bfloat162float(h0)),
                        __float2bfloat16(v.y - __bfloat162float(h1))};
    __nv_bfloat162 d = {__float2bfloat16(v.z - __bfloat162float(h2)),
                        __float2bfloat16(v.w - __bfloat162float(h3))};
    ((uint2*)lo)[i] = make_uint2(*(uint32_t*)&c, *(uint32_t*)&d);
}

__global__ __launch_bounds__(256)
void convert_w_all(const float* __restrict__ W0, const float* __restrict__ W1,
                   const float* __restrict__ W2,
                   __nv_bfloat16* __restrict__ w0hi, __nv_bfloat16* __restrict__ w0lo,
                   __nv_bfloat16* __restrict__ w1hi, __nv_bfloat16* __restrict__ w1lo,
                   __nv_bfloat16* __restrict__ w2hi, __nv_bfloat16* __restrict__ w2lo) {
    int i = blockIdx.x * blockDim.x + threadIdx.x;   // 0 .. 288*256-1
    const float* W; __nv_bfloat16 *hi, *lo; int N, base;
    if (i < 128 * 256)      { W = W0; hi = w0hi; lo = w0lo; N = 128; base = 0; }
    else if (i < 256 * 256) { W = W1; hi = w1hi; lo = w1lo; N = 128; base = 128 * 256; }
    else if (i < 288 * 256) { W = W2; hi = w2hi; lo = w2lo; N = 32;  base = 256 * 256; }
    else return;
    int li = i - base;
    int n = li >> 8, k = li & 255;
    float v = W[(size_t)k * N + n];
    __nv_bfloat16 h = __float2bfloat16(v);
    hi[li] = h;
    lo[li] = __float2bfloat16(v - __bfloat162float(h));
}

// ---------------- pipelined ldmatrix GEMM --------------------------------------
template <int NT>
__device__ __forceinline__ void gload(uint32_t sbase, const uint4* Ahi4, const uint4* Alo4,
                                      const uint4* Bhi4, const uint4* Blo4,
                                      int m0, int M, int ch, int tid) {
    const uint32_t sAhi = sbase;
    const uint32_t sAlo = sbase + 128 * 80;
    const uint32_t sBhi = sbase + 256 * 80;
    const uint32_t sBlo = sbase + 256 * 80 + NT * 80;
#pragma unroll
    for (int j = 0; j < 2; j++) {
        int i   = tid + j * 256;
        int row = i >> 2, c4 = i & 3;
        int gr  = m0 + row;
        int ok  = (gr < M) ? 16 : 0;
        size_t g = (size_t)(ok ? gr : 0) * 32 + ch * 4 + c4;
        cpasync16(sAhi + row * 80 + c4 * 16, Ahi4 + g, ok);
        cpasync16(sAlo + row * 80 + c4 * 16, Alo4 + g, ok);
    }
#pragma unroll
    for (int j = 0; j < (NT * 4 + 255) / 256; j++) {
        int i = tid + j * 256;
        if (i < NT * 4) {
            int row = i >> 2, c4 = i & 3;
            size_t g = (size_t)row * 32 + ch * 4 + c4;
            cpasync16(sBhi + row * 80 + c4 * 16, Bhi4 + g, 16);
            cpasync16(sBlo + row * 80 + c4 * 16, Blo4 + g, 16);
        }
    }
}

template <int NT>
__global__ __launch_bounds__(256, 2)
void gemm_mma3(const __nv_bfloat16* __restrict__ Ahi, const __nv_bfloat16* __restrict__ Alo,
               const __nv_bfloat16* __restrict__ Bhi, const __nv_bfloat16* __restrict__ Blo,
               float* __restrict__ C, int M) {
    constexpr int WNT   = NT / 16;
    constexpr int STAGE = (256 + 2 * NT) * 80;
    extern __shared__ char sm[];
    const uint32_t smu = smem_u32(sm);

    const int tid  = threadIdx.x;
    const int wid  = tid >> 5;
    const int lane = tid & 31;
    const int wm   = wid & 3;
    const int wn   = wid >> 2;
    const int m0   = blockIdx.x * 128;
    const int r    = lane >> 2;
    const int c2   = (lane & 3) * 2;

    const uint32_t aOff = (uint32_t)(lane & 15) * 80 + ((lane & 16) ? 16u : 0u);
    const uint32_t bOff = (uint32_t)((lane & 7) + ((lane & 16) ? 8 : 0)) * 80 +
                          ((lane & 8) ? 16u : 0u);

    const uint4* Ahi4 = (const uint4*)Ahi;
    const uint4* Alo4 = (const uint4*)Alo;
    const uint4* Bhi4 = (const uint4*)Bhi;
    const uint4* Blo4 = (const uint4*)Blo;

    float acc[2][WNT][4];
#pragma unroll
    for (int mt = 0; mt < 2; mt++)
#pragma unroll
        for (int j = 0; j < WNT; j++)
#pragma unroll
            for (int q = 0; q < 4; q++) acc[mt][j][q] = 0.0f;

    gload<NT>(smu, Ahi4, Alo4, Bhi4, Blo4, m0, M, 0, tid);
    CP_COMMIT();

    for (int ch = 0; ch < 8; ch++) {
        if (ch < 7) {
            gload<NT>(smu + ((ch + 1) & 1) * STAGE, Ahi4, Alo4, Bhi4, Blo4, m0, M, ch + 1, tid);
            CP_COMMIT();
            asm volatile("cp.async.wait_group 1;" ::: "memory");
        } else {
            asm volatile("cp.async.wait_group 0;" ::: "memory");
        }
        __syncthreads();

        const uint32_t st = smu + (ch & 1) * STAGE;

#pragma unroll
        for (int ks = 0; ks < 2; ks++) {
            const uint32_t k0b = ks * 32;
            uint32_t ah[2][4], al[2][4];
#pragma unroll
            for (int mt = 0; mt < 2; mt++) {
                uint32_t rowb = (uint32_t)(wm * 32 + mt * 16) * 80;
                ldsm4(ah[mt], st + rowb + aOff + k0b);
                ldsm4(al[mt], st + 128 * 80 + rowb + aOff + k0b);
            }
#pragma unroll
            for (int p = 0; p < WNT / 2; p++) {
                uint32_t n0b = (uint32_t)(wn * (NT / 2) + p * 16) * 80;
                uint32_t ba = st + 256 * 80 + n0b + bOff + k0b;
                uint32_t bh4[4], bl4[4];
                ldsm4(bh4, ba);
                ldsm4(bl4, ba + NT * 80);
#pragma unroll
                for (int jj = 0; jj < 2; jj++) {
                    int j = p * 2 + jj;
#pragma unroll
                    for (int mt = 0; mt < 2; mt++) {
                        mma16816(acc[mt][j], ah[mt], bh4 + jj * 2);
                        mma16816(acc[mt][j], ah[mt], bl4 + jj * 2);
                        mma16816(acc[mt][j], al[mt], bh4 + jj * 2);
                    }
                }
            }
        }
        __syncthreads();
    }

#pragma unroll
    for (int mt = 0; mt < 2; mt++) {
        int row0 = m0 + wm * 32 + mt * 16 + r;
#pragma unroll
        for (int j = 0; j < WNT; j++) {
            int col = wn * (NT / 2) + j * 8 + c2;
            if (row0 < M)
                *(float2*)&C[(size_t)row0 * NT + col] = make_float2(acc[mt][j][0], acc[mt][j][1]);
            if (row0 + 8 < M)
                *(float2*)&C[(size_t)(row0 + 8) * NT + col] = make_float2(acc[mt][j][2], acc[mt][j][3]);
        }
    }
}

// ---------------- BN apply + ReLU + concat -> bf16 hi/lo ------------------------
__global__ __launch_bounds__(256)
void bn_apply_concat4(const float* __restrict__ pre, const float* __restrict__ stats,
                      const float* __restrict__ gamma, const float* __restrict__ beta,
                      __nv_bfloat16* __restrict__ xhi, __nv_bfloat16* __restrict__ xlo) {
    int idx4 = blockIdx.x * blockDim.x + threadIdx.x;
    if (idx4 >= N_NODES * 32) return;
    int r = idx4 >> 5;
    int c = (idx4 & 31) * 4;
    const float invN = 1.0f / (float)N_NODES;
    float4 v = *(const float4*)(pre + (size_t)r * 128 + c);
    float vv[4] = {v.x, v.y, v.z, v.w};
    float hv[4];
#pragma unroll
    for (int qd = 0; qd < 4; qd++) {
        float mu  = stats[c + qd] * invN;
        float var = stats[128 + c + qd] * invN - mu * mu;
        float inv = rsqrtf(var + BN_EPS);
        float bn  = (vv[qd] - mu) * inv * gamma[c + qd] + beta[c + qd];
        hv[qd] = bn > 0.0f ? bn : 0.0f;
    }
    size_t o0 = (size_t)r * 256 + c;
    {
        __nv_bfloat16 h0 = __float2bfloat16(hv[0]), h1 = __float2bfloat16(hv[1]);
        __nv_bfloat16 h2 = __float2bfloat16(hv[2]), h3 = __float2bfloat16(hv[3]);
        __nv_bfloat162 a = {h0, h1}, b = {h2, h3};
        *(uint2*)(xhi + o0) = make_uint2(*(uint32_t*)&a, *(uint32_t*)&b);
        __nv_bfloat162 la = {__float2bfloat16(hv[0] - __bfloat162float(h0)),
                             __float2bfloat16(hv[1] - __bfloat162float(h1))};
        __nv_bfloat162 lb = {__float2bfloat16(hv[2] - __bfloat162float(h2)),
                             __float2bfloat16(hv[3] - __bfloat162float(h3))};
        *(uint2*)(xlo + o0) = make_uint2(*(uint32_t*)&la, *(uint32_t*)&lb);
    }
    {
        __nv_bfloat16 h0 = __float2bfloat16(vv[0]), h1 = __float2bfloat16(vv[1]);
        __nv_bfloat16 h2 = __float2bfloat16(vv[2]), h3 = __float2bfloat16(vv[3]);
        __nv_bfloat162 a = {h0, h1}, b = {h2, h3};
        *(uint2*)(xhi + o0 + 128) = make_uint2(*(uint32_t*)&a, *(uint32_t*)&b);
        __nv_bfloat162 la = {__float2bfloat16(vv[0] - __bfloat162float(h0)),
                             __float2bfloat16(vv[1] - __bfloat162float(h1))};
        __nv_bfloat162 lb = {__float2bfloat16(vv[2] - __bfloat162float(h2)),
                             __float2bfloat16(vv[3] - __bfloat162float(h3))};
        *(uint2*)(xlo + o0 + 128) = make_uint2(*(uint32_t*)&la, *(uint32_t*)&lb);
    }
}

// ---------------- launch ---------------------------------------------------------
extern "C" void kernel_launch(void* const* d_in, const int* in_sizes, int n_in,
                              void* d_out, int out_size) {
    const float* x      = (const float*)d_in[0];
    const int*   src    = (const int*)  d_in[1];
    const int*   dst    = (const int*)  d_in[2];
    const float* ew     = (const float*)d_in[3];
    const float* W0     = (const float*)d_in[4];
    const float* W1     = (const float*)d_in[5];
    const float* W2     = (const float*)d_in[6];
    const float* gamma0 = (const float*)d_in[7];
    const float* beta0  = (const float*)d_in[8];
    const float* gamma1 = (const float*)d_in[9];
    const float* beta1  = (const float*)d_in[10];
    float* out = (float*)d_out;

    __nv_bfloat16 *xhi, *xlo, *w0hi, *w0lo, *w1hi, *w1lo, *w2hi, *w2lo;
    float *proj, *pre, *stats;
    int *deg, *cur, *off;
    int2 *erec;
    cudaGetSymbolAddress((void**)&xhi,   g_xhi);
    cudaGetSymbolAddress((void**)&xlo,   g_xlo);
    cudaGetSymbolAddress((void**)&w0hi,  g_w0hi);
    cudaGetSymbolAddress((void**)&w0lo,  g_w0lo);
    cudaGetSymbolAddress((void**)&w1hi,  g_w1hi);
    cudaGetSymbolAddress((void**)&w1lo,  g_w1lo);
    cudaGetSymbolAddress((void**)&w2hi,  g_w2hi);
    cudaGetSymbolAddress((void**)&w2lo,  g_w2lo);
    cudaGetSymbolAddress((void**)&proj,  g_proj);
    cudaGetSymbolAddress((void**)&pre,   g_pre);
    cudaGetSymbolAddress((void**)&stats, g_stats);
    cudaGetSymbolAddress((void**)&deg,   g_deg);
    cudaGetSymbolAddress((void**)&cur,   g_cur);
    cudaGetSymbolAddress((void**)&off,   g_off);
    cudaGetSymbolAddress((void**)&erec,  g_erec);

    // one-time resources (created before graph capture, on the correctness call)
    static cudaStream_t sSide = nullptr;
    static cudaEvent_t evFork = nullptr, evJoin = nullptr;
    if (sSide == nullptr) {
        cudaStreamCreateWithFlags(&sSide, cudaStreamNonBlocking);
        cudaEventCreateWithFlags(&evFork, cudaEventDisableTiming);
        cudaEventCreateWithFlags(&evJoin, cudaEventDisableTiming);
    }

    const int smem128 = 2 * (256 + 2 * 128) * 80;   // 81920
    const int smem32  = 2 * (256 + 2 * 32)  * 80;   // 51200
    cudaFuncSetAttribute(gemm_mma3<128>, cudaFuncAttributeMaxDynamicSharedMemorySize, smem128);
    cudaFuncSetAttribute(gemm_mma3<32>,  cudaFuncAttributeMaxDynamicSharedMemorySize, smem32);

    const int nX4      = N_NODES * 256 / 4;
    const int bnBlocks = (N_NODES * 32 + 255) / 256;
    const int mTiles   = (N_NODES + 127) / 128;          // 391
    const int edgeB4   = (N_EDGES / 4 + 255) / 256;      // 782
    const int aggB128  = 148 * 8;                        // 1184: full occupancy
    const int aggB32   = (N_NODES * 8 + 255) / 256;      // 1563

    // ---- fork: CSR build on side stream, concurrent with converts + gemm0 ----
    cudaEventRecord(evFork, 0);
    cudaStreamWaitEvent(sSide, evFork, 0);
    csr_zero<<<(N_NODES + 255) / 256, 256, 0, sSide>>>(deg, stats);
    csr_hist<<<edgeB4, 256, 0, sSide>>>(dst, deg);
    csr_scan<<<1, 1024, 0, sSide>>>(deg, off, cur);
    csr_fill<<<edgeB4, 256, 0, sSide>>>(src, dst, ew, cur, erec);
    cudaEventRecord(evJoin, sSide);

    // ---- main stream: converts + layer-0 GEMM ----
    convert_x4<<<(nX4 + 255) / 256, 256>>>(x, xhi, xlo, nX4);
    convert_w_all<<<(288 * 256 + 255) / 256, 256>>>(W0, W1, W2, w0hi, w0lo,
                                                    w1hi, w1lo, w2hi, w2lo);
    gemm_mma3<128><<<mTiles, 256, smem128>>>(xhi, xlo, w0hi, w0lo, proj, N_NODES);

    // ---- join: aggregation needs the CSR ----
    cudaStreamWaitEvent(0, evJoin, 0);

    // ---- layer 0 ----
    agg128_stats<<<aggB128, 256>>>(proj, off, erec, pre, stats);
    bn_apply_concat4<<<bnBlocks, 256>>>(pre, stats, gamma0, beta0, xhi, xlo);

    // ---- layer 1 ----
    gemm_mma3<128><<<mTiles, 256, smem128>>>(xhi, xlo, w1hi, w1lo, proj, N_NODES);
    agg128_stats<<<aggB128, 256>>>(proj, off, erec, pre, stats + 256);
    bn_apply_concat4<<<bnBlocks, 256>>>(pre, stats + 256, gamma1, beta1, xhi, xlo);

    // ---- output layer (N=32) ----
    gemm_mma3<32><<<mTiles, 256, smem32>>>(xhi, xlo, w2hi, w2lo, proj, N_NODES);
    agg_csr32<<<aggB32, 256>>>(proj, off, erec, out);
}

// round 8
// speedup vs baseline: 1.3336x; 1.1628x over previous
#include <cuda_runtime.h>
#include <cuda_bf16.h>
#include <cstdint>
#include <cstddef>

#define N_NODES 50000
#define N_EDGES 800000
#define BN_EPS  1e-5f

// ---------------- scratch (static device globals; allocation-free) ----------
__device__ __nv_bfloat16 g_w0hi[128 * 256], g_w0lo[128 * 256];
__device__ __nv_bfloat16 g_w1hi[128 * 256], g_w1lo[128 * 256];
__device__ __nv_bfloat16 g_w2hi[32 * 256],  g_w2lo[32 * 256];
__device__ float g_proj[(size_t)N_NODES * 128];
__device__ float g_pre [(size_t)N_NODES * 128];
__device__ float g_stats[512];                 // layer0: [0:256), layer1: [256:512)
__device__ int   g_deg[N_NODES];
__device__ int   g_cur[N_NODES];
__device__ int   g_off[N_NODES + 1];
__device__ int2  g_erec[N_EDGES];              // (src, w bits), grouped by dst

// ---------------- asm helpers ------------------------------------------------
__device__ __forceinline__ void mma16816(float* d, const uint32_t* a, const uint32_t* b) {
    asm volatile(
        "mma.sync.aligned.m16n8k16.row.col.f32.bf16.bf16.f32 "
        "{%0,%1,%2,%3}, {%4,%5,%6,%7}, {%8,%9}, {%0,%1,%2,%3};"
        : "+f"(d[0]), "+f"(d[1]), "+f"(d[2]), "+f"(d[3])
        : "r"(a[0]), "r"(a[1]), "r"(a[2]), "r"(a[3]), "r"(b[0]), "r"(b[1]));
}
__device__ __forceinline__ void ldsm4(uint32_t* r, uint32_t a) {
    asm volatile("ldmatrix.sync.aligned.m8n8.x4.shared.b16 {%0,%1,%2,%3}, [%4];"
                 : "=r"(r[0]), "=r"(r[1]), "=r"(r[2]), "=r"(r[3]) : "r"(a));
}
__device__ __forceinline__ uint32_t smem_u32(const void* p) {
    uint32_t a;
    asm("{ .reg .u64 t; cvta.to.shared.u64 t, %1; cvt.u32.u64 %0, t; }" : "=r"(a) : "l"(p));
    return a;
}
__device__ __forceinline__ void cpasync16(uint32_t dst, const void* src, int src_sz) {
    asm volatile("cp.async.ca.shared.global [%0], [%1], 16, %2;"
                 :: "r"(dst), "l"(src), "r"(src_sz));
}
#define CP_COMMIT() asm volatile("cp.async.commit_group;" ::: "memory")
__device__ __forceinline__ void redg_v4(float* p, float4 v) {
    asm volatile("red.global.add.v4.f32 [%0], {%1,%2,%3,%4};"
                 :: "l"(p), "f"(v.x), "f"(v.y), "f"(v.z), "f"(v.w) : "memory");
}
__device__ __forceinline__ void sts16(uint32_t a, uint32_t r0, uint32_t r1,
                                      uint32_t r2, uint32_t r3) {
    asm volatile("st.shared.v4.b32 [%0], {%1,%2,%3,%4};"
                 :: "r"(a), "r"(r0), "r"(r1), "r"(r2), "r"(r3) : "memory");
}
__device__ __forceinline__ float4 lds16(uint32_t a) {
    float4 v;
    asm volatile("ld.shared.v4.f32 {%0,%1,%2,%3}, [%4];"
                 : "=f"(v.x), "=f"(v.y), "=f"(v.z), "=f"(v.w) : "r"(a));
    return v;
}

// ---------------- CSR build ---------------------------------------------------
__global__ __launch_bounds__(256)
void csr_zero(int* __restrict__ deg, float* __restrict__ stats) {
    int i = blockIdx.x * blockDim.x + threadIdx.x;
    if (i < N_NODES) deg[i] = 0;
    if (i < 512) stats[i] = 0.0f;
}
__global__ __launch_bounds__(256)
void csr_hist(const int* __restrict__ dst, int* __restrict__ deg) {
    int b = (blockIdx.x * blockDim.x + threadIdx.x) * 4;
    if (b + 3 < N_EDGES) {
        int4 d = *(const int4*)(dst + b);
        atomicAdd(&deg[d.x], 1);
        atomicAdd(&deg[d.y], 1);
        atomicAdd(&deg[d.z], 1);
        atomicAdd(&deg[d.w], 1);
    } else {
        for (int e = b; e < N_EDGES; e++) atomicAdd(&deg[dst[e]], 1);
    }
}
__global__ __launch_bounds__(1024)
void csr_scan(const int* __restrict__ deg, int* __restrict__ off, int* __restrict__ cur) {
    __shared__ int wsum[32];
    const int t = threadIdx.x;
    const int base = t * 49;
    int s = 0;
#pragma unroll 7
    for (int k = 0; k < 49; k++) {
        int idx = base + k;
        if (idx < N_NODES) s += deg[idx];
    }
    int v = s;
#pragma unroll
    for (int o = 1; o < 32; o <<= 1) {
        int u = __shfl_up_sync(0xFFFFFFFFu, v, o);
        if ((t & 31) >= o) v += u;
    }
    if ((t & 31) == 31) wsum[t >> 5] = v;
    __syncthreads();
    if (t < 32) {
        int w = wsum[t];
#pragma unroll
        for (int o = 1; o < 32; o <<= 1) {
            int u = __shfl_up_sync(0xFFFFFFFFu, w, o);
            if (t >= o) w += u;
        }
        wsum[t] = w;
    }
    __syncthreads();
    int run = v - s + ((t >= 32) ? wsum[(t >> 5) - 1] : 0);
#pragma unroll 7
    for (int k = 0; k < 49; k++) {
        int idx = base + k;
        if (idx < N_NODES) {
            off[idx] = run;
            cur[idx] = run;
            run += deg[idx];
        }
    }
    if (t == 1023) off[N_NODES] = run;
}
__global__ __launch_bounds__(256)
void csr_fill(const int* __restrict__ src, const int* __restrict__ dst,
              const float* __restrict__ w, int* __restrict__ cur, int2* __restrict__ erec) {
    int b = (blockIdx.x * blockDim.x + threadIdx.x) * 4;
    if (b + 3 < N_EDGES) {
        int4   s = *(const int4*)(src + b);
        int4   d = *(const int4*)(dst + b);
        float4 v = *(const float4*)(w + b);
        int p0 = atomicAdd(&cur[d.x], 1);
        int p1 = atomicAdd(&cur[d.y], 1);
        int p2 = atomicAdd(&cur[d.z], 1);
        int p3 = atomicAdd(&cur[d.w], 1);
        erec[p0] = make_int2(s.x, __float_as_int(v.x));
        erec[p1] = make_int2(s.y, __float_as_int(v.y));
        erec[p2] = make_int2(s.z, __float_as_int(v.z));
        erec[p3] = make_int2(s.w, __float_as_int(v.w));
    } else {
        for (int e = b; e < N_EDGES; e++) {
            int pos = atomicAdd(&cur[dst[e]], 1);
            erec[pos] = make_int2(src[e], __float_as_int(w[e]));
        }
    }
}

// ---------------- fused CSR aggregation + BN stats (width 128) -----------------
__global__ __launch_bounds__(256)
void agg128_stats(const float* __restrict__ h, const int* __restrict__ off,
                  const int2* __restrict__ erec, float* __restrict__ out,
                  float* __restrict__ stats) {
    const int warp = threadIdx.x >> 5;
    const int lane = threadIdx.x & 31;
    const float4* h4 = (const float4*)h;
    float4 S = make_float4(0.f, 0.f, 0.f, 0.f);
    float4 Q = make_float4(0.f, 0.f, 0.f, 0.f);

    for (int n = blockIdx.x * 8 + warp; n < N_NODES; n += gridDim.x * 8) {
        int i = off[n], end = off[n + 1];
        float4 acc = make_float4(0.f, 0.f, 0.f, 0.f);
        for (; i + 1 < end; i += 2) {
            int2 r0 = erec[i], r1 = erec[i + 1];
            float w0 = __int_as_float(r0.y), w1 = __int_as_float(r1.y);
            float4 v0 = h4[(size_t)r0.x * 32 + lane];
            float4 v1 = h4[(size_t)r1.x * 32 + lane];
            acc.x += w0 * v0.x + w1 * v1.x;
            acc.y += w0 * v0.y + w1 * v1.y;
            acc.z += w0 * v0.z + w1 * v1.z;
            acc.w += w0 * v0.w + w1 * v1.w;
        }
        if (i < end) {
            int2 r0 = erec[i];
            float w0 = __int_as_float(r0.y);
            float4 v0 = h4[(size_t)r0.x * 32 + lane];
            acc.x += w0 * v0.x; acc.y += w0 * v0.y;
            acc.z += w0 * v0.z; acc.w += w0 * v0.w;
        }
        ((float4*)out)[(size_t)n * 32 + lane] = acc;
        S.x += acc.x; S.y += acc.y; S.z += acc.z; S.w += acc.w;
        Q.x += acc.x * acc.x; Q.y += acc.y * acc.y;
        Q.z += acc.z * acc.z; Q.w += acc.w * acc.w;
    }

    __shared__ float4 sS[8][32], sQ[8][32];
    sS[warp][lane] = S;
    sQ[warp][lane] = Q;
    __syncthreads();
    if (warp == 0) {
        float4 TS = sS[0][lane], TQ = sQ[0][lane];
#pragma unroll
        for (int g = 1; g < 8; g++) {
            float4 a = sS[g][lane], b = sQ[g][lane];
            TS.x += a.x; TS.y += a.y; TS.z += a.z; TS.w += a.w;
            TQ.x += b.x; TQ.y += b.y; TQ.z += b.z; TQ.w += b.w;
        }
        redg_v4(stats + lane * 4, TS);
        redg_v4(stats + 128 + lane * 4, TQ);
    }
}

// width 32: 8 lanes per node
__global__ __launch_bounds__(256)
void agg_csr32(const float* __restrict__ h, const int* __restrict__ off,
               const int2* __restrict__ erec, float* __restrict__ out) {
    int gid = blockIdx.x * blockDim.x + threadIdx.x;
    int n = gid >> 3;
    int sl = gid & 7;
    if (n >= N_NODES) return;
    int i = off[n], end = off[n + 1];
    const float4* h4 = (const float4*)h;
    float4 acc = make_float4(0.f, 0.f, 0.f, 0.f);
    for (; i + 1 < end; i += 2) {
        int2 r0 = erec[i], r1 = erec[i + 1];
        float w0 = __int_as_float(r0.y), w1 = __int_as_float(r1.y);
        float4 v0 = h4[(size_t)r0.x * 8 + sl];
        float4 v1 = h4[(size_t)r1.x * 8 + sl];
        acc.x += w0 * v0.x + w1 * v1.x;
        acc.y += w0 * v0.y + w1 * v1.y;
        acc.z += w0 * v0.z + w1 * v1.z;
        acc.w += w0 * v0.w + w1 * v1.w;
    }
    if (i < end) {
        int2 r0 = erec[i];
        float w0 = __int_as_float(r0.y);
        float4 v0 = h4[(size_t)r0.x * 8 + sl];
        acc.x += w0 * v0.x; acc.y += w0 * v0.y;
        acc.z += w0 * v0.z; acc.w += w0 * v0.w;
    }
    ((float4*)out)[(size_t)n * 8 + sl] = acc;
}

// ---------------- weight conversion --------------------------------------------
__global__ __launch_bounds__(256)
void convert_w_all(const float* __restrict__ W0, const float* __restrict__ W1,
                   const float* __restrict__ W2,
                   __nv_bfloat16* __restrict__ w0hi, __nv_bfloat16* __restrict__ w0lo,
                   __nv_bfloat16* __restrict__ w1hi, __nv_bfloat16* __restrict__ w1lo,
                   __nv_bfloat16* __restrict__ w2hi, __nv_bfloat16* __restrict__ w2lo) {
    int i = blockIdx.x * blockDim.x + threadIdx.x;   // 0 .. 288*256-1
    const float* W; __nv_bfloat16 *hi, *lo; int N, base;
    if (i < 128 * 256)      { W = W0; hi = w0hi; lo = w0lo; N = 128; base = 0; }
    else if (i < 256 * 256) { W = W1; hi = w1hi; lo = w1lo; N = 128; base = 128 * 256; }
    else if (i < 288 * 256) { W = W2; hi = w2hi; lo = w2lo; N = 32;  base = 256 * 256; }
    else return;
    int li = i - base;
    int n = li >> 8, k = li & 255;
    float v = W[(size_t)k * N + n];
    __nv_bfloat16 h = __float2bfloat16(v);
    hi[li] = h;
    lo[li] = __float2bfloat16(v - __bfloat162float(h));
}

// ---------------- fused GEMM: fp32 A -> (BN/ReLU/concat) -> bf16 hi/lo -> MMA ---
// BN=false: A = Af32 [M, 256], plain convert. srcStride = 256.
// BN=true : logical A = [relu(bn(pre)) | pre], pre = Af32 [M, 128]. srcStride = 128.
// C[M, NT] = A @ Wt[NT,256]^T.  CTA 128xNT, 8 warps (4m x 2n), BK=32, 2-stage.
//
// smem layout:
//   0                : Af32 stage0  (128 rows x 144B)   18432
//   18432            : Af32 stage1                       18432
//   36864            : Abf hi (128 x 80B)                10240
//   47104            : Abf lo                            10240
//   57344            : B stage0 hi (NT x 80B), lo
//   57344 + 2*NT*80  : B stage1 hi, lo
template <int NT, bool BN>
__global__ __launch_bounds__(256, 2)
void gemm_fused(const float* __restrict__ Af32,
                const __nv_bfloat16* __restrict__ Bhi, const __nv_bfloat16* __restrict__ Blo,
                const float* __restrict__ stats, const float* __restrict__ gamma,
                const float* __restrict__ beta,
                float* __restrict__ C, int M) {
    constexpr int WNT    = NT / 16;
    constexpr int AF_ST  = 18432;
    constexpr int ABF_HI = 36864;
    constexpr int ABF_LO = 47104;
    constexpr int B_BASE = 57344;
    constexpr int B_ST   = 2 * NT * 80;
    constexpr int SRC_STRIDE4 = BN ? 32 : 64;        // uint4 per A row
    extern __shared__ char sm[];
    const uint32_t smu = smem_u32(sm);
    __shared__ float bnmul[128], bnadd[128];

    const int tid  = threadIdx.x;
    const int wid  = tid >> 5;
    const int lane = tid & 31;
    const int wm   = wid & 3;
    const int wn   = wid >> 2;
    const int m0   = blockIdx.x * 128;
    const int r    = lane >> 2;
    const int c2   = (lane & 3) * 2;

    const uint32_t aOff = (uint32_t)(lane & 15) * 80 + ((lane & 16) ? 16u : 0u);
    const uint32_t bOff = (uint32_t)((lane & 7) + ((lane & 16) ? 8 : 0)) * 80 +
                          ((lane & 8) ? 16u : 0u);

    if (BN && tid < 128) {
        const float invN = 1.0f / (float)N_NODES;
        float mu  = stats[tid] * invN;
        float var = stats[128 + tid] * invN - mu * mu;
        float inv = rsqrtf(var + BN_EPS) * gamma[tid];
        bnmul[tid] = inv;
        bnadd[tid] = beta[tid] - mu * inv;
    }

    const uint4* A4   = (const uint4*)Af32;
    const uint4* Bhi4 = (const uint4*)Bhi;
    const uint4* Blo4 = (const uint4*)Blo;

    float acc[2][WNT][4];
#pragma unroll
    for (int mt = 0; mt < 2; mt++)
#pragma unroll
        for (int j = 0; j < WNT; j++)
#pragma unroll
            for (int q = 0; q < 4; q++) acc[mt][j][q] = 0.0f;

    // ---- loader lambda-equivalent: stage s gets chunk ch ----
    auto load_stage = [&](int s, int ch) {
        const int srcCh = BN ? (ch & 3) : ch;        // source uint4 offset base
        const uint32_t stA = smu + s * AF_ST;
#pragma unroll
        for (int j = 0; j < 4; j++) {                // A f32: 128 rows x 8 uint4
            int i   = tid + j * 256;
            int row = i >> 3, c16 = i & 7;
            int gr  = m0 + row;
            int ok  = (gr < M) ? 16 : 0;
            size_t g = (size_t)(ok ? gr : 0) * SRC_STRIDE4 + srcCh * 8 + c16;
            cpasync16(stA + row * 144 + c16 * 16, A4 + g, ok);
        }
        const uint32_t stBhi = smu + B_BASE + s * B_ST;
        const uint32_t stBlo = stBhi + NT * 80;
#pragma unroll
        for (int j = 0; j < (NT * 4 + 255) / 256; j++) {   // B: NT rows x 4 uint4/plane
            int i = tid + j * 256;
            if (i < NT * 4) {
                int row = i >> 2, c4 = i & 3;
                size_t g = (size_t)row * 32 + ch * 4 + c4;
                cpasync16(stBhi + row * 80 + c4 * 16, Bhi4 + g, 16);
                cpasync16(stBlo + row * 80 + c4 * 16, Blo4 + g, 16);
            }
        }
    };

    load_stage(0, 0);
    CP_COMMIT();

    const int tr_r = tid >> 1;                 // transform: row 0..127
    const int tr_c = (tid & 1) * 16;           // 16 cols per thread

    for (int ch = 0; ch < 8; ch++) {
        if (ch < 7) {
            load_stage((ch + 1) & 1, ch + 1);
            CP_COMMIT();
            asm volatile("cp.async.wait_group 1;" ::: "memory");
        } else {
            asm volatile("cp.async.wait_group 0;" ::: "memory");
        }
        __syncthreads();      // staged f32 + B ready; Abf free (prev MMA done)

        // ---- transform: staged f32 -> Abf hi/lo (bn+relu for BN & ch<4) ----
        {
            const uint32_t stA = smu + (ch & 1) * AF_ST + tr_r * 144 + tr_c * 4;
            float f[16];
#pragma unroll
            for (int q = 0; q < 4; q++) {
                float4 v = lds16(stA + q * 16);
                f[q * 4 + 0] = v.x; f[q * 4 + 1] = v.y;
                f[q * 4 + 2] = v.z; f[q * 4 + 3] = v.w;
            }
            if (BN && ch < 4) {
                const int c0 = ch * 32 + tr_c;
#pragma unroll
                for (int e = 0; e < 16; e++)
                    f[e] = fmaxf(f[e] * bnmul[c0 + e] + bnadd[c0 + e], 0.0f);
            }
            uint32_t h2[8], l2[8];
#pragma unroll
            for (int e = 0; e < 8; e++) {
                __nv_bfloat16 ha = __float2bfloat16(f[e * 2]);
                __nv_bfloat16 hb = __float2bfloat16(f[e * 2 + 1]);
                __nv_bfloat162 hp = {ha, hb};
                h2[e] = *(uint32_t*)&hp;
                __nv_bfloat162 lp = {__float2bfloat16(f[e * 2] - __bfloat162float(ha)),
                                     __float2bfloat16(f[e * 2 + 1] - __bfloat162float(hb))};
                l2[e] = *(uint32_t*)&lp;
            }
            const uint32_t dHi = smu + ABF_HI + tr_r * 80 + tr_c * 2;
            const uint32_t dLo = smu + ABF_LO + tr_r * 80 + tr_c * 2;
            sts16(dHi,      h2[0], h2[1], h2[2], h2[3]);
            sts16(dHi + 16, h2[4], h2[5], h2[6], h2[7]);
            sts16(dLo,      l2[0], l2[1], l2[2], l2[3]);
            sts16(dLo + 16, l2[4], l2[5], l2[6], l2[7]);
        }
        __syncthreads();      // Abf visible

        // ---- MMA ----
        const uint32_t stBhi = smu + B_BASE + (ch & 1) * B_ST;
#pragma unroll
        for (int ks = 0; ks < 2; ks++) {
            const uint32_t k0b = ks * 32;
            uint32_t ah[2][4], al[2][4];
#pragma unroll
            for (int mt = 0; mt < 2; mt++) {
                uint32_t rowb = (uint32_t)(wm * 32 + mt * 16) * 80;
                ldsm4(ah[mt], smu + ABF_HI + rowb + aOff + k0b);
                ldsm4(al[mt], smu + ABF_LO + rowb + aOff + k0b);
            }
#pragma unroll
            for (int p = 0; p < WNT / 2; p++) {
                uint32_t n0b = (uint32_t)(wn * (NT / 2) + p * 16) * 80;
                uint32_t ba = stBhi + n0b + bOff + k0b;
                uint32_t bh4[4], bl4[4];
                ldsm4(bh4, ba);
                ldsm4(bl4, ba + NT * 80);
#pragma unroll
                for (int jj = 0; jj < 2; jj++) {
                    int j = p * 2 + jj;
#pragma unroll
                    for (int mt = 0; mt < 2; mt++) {
                        mma16816(acc[mt][j], ah[mt], bh4 + jj * 2);
                        mma16816(acc[mt][j], ah[mt], bl4 + jj * 2);
                        mma16816(acc[mt][j], al[mt], bh4 + jj * 2);
                    }
                }
            }
        }
        __syncthreads();      // MMA done before next transform/loads overwrite
    }

#pragma unroll
    for (int mt = 0; mt < 2; mt++) {
        int row0 = m0 + wm * 32 + mt * 16 + r;
#pragma unroll
        for (int j = 0; j < WNT; j++) {
            int col = wn * (NT / 2) + j * 8 + c2;
            if (row0 < M)
                *(float2*)&C[(size_t)row0 * NT + col] = make_float2(acc[mt][j][0], acc[mt][j][1]);
            if (row0 + 8 < M)
                *(float2*)&C[(size_t)(row0 + 8) * NT + col] = make_float2(acc[mt][j][2], acc[mt][j][3]);
        }
    }
}

// ---------------- launch ---------------------------------------------------------
extern "C" void kernel_launch(void* const* d_in, const int* in_sizes, int n_in,
                              void* d_out, int out_size) {
    const float* x      = (const float*)d_in[0];
    const int*   src    = (const int*)  d_in[1];
    const int*   dst    = (const int*)  d_in[2];
    const float* ew     = (const float*)d_in[3];
    const float* W0     = (const float*)d_in[4];
    const float* W1     = (const float*)d_in[5];
    const float* W2     = (const float*)d_in[6];
    const float* gamma0 = (const float*)d_in[7];
    const float* beta0  = (const float*)d_in[8];
    const float* gamma1 = (const float*)d_in[9];
    const float* beta1  = (const float*)d_in[10];
    float* out = (float*)d_out;

    __nv_bfloat16 *w0hi, *w0lo, *w1hi, *w1lo, *w2hi, *w2lo;
    float *proj, *pre, *stats;
    int *deg, *cur, *off;
    int2 *erec;
    cudaGetSymbolAddress((void**)&w0hi,  g_w0hi);
    cudaGetSymbolAddress((void**)&w0lo,  g_w0lo);
    cudaGetSymbolAddress((void**)&w1hi,  g_w1hi);
    cudaGetSymbolAddress((void**)&w1lo,  g_w1lo);
    cudaGetSymbolAddress((void**)&w2hi,  g_w2hi);
    cudaGetSymbolAddress((void**)&w2lo,  g_w2lo);
    cudaGetSymbolAddress((void**)&proj,  g_proj);
    cudaGetSymbolAddress((void**)&pre,   g_pre);
    cudaGetSymbolAddress((void**)&stats, g_stats);
    cudaGetSymbolAddress((void**)&deg,   g_deg);
    cudaGetSymbolAddress((void**)&cur,   g_cur);
    cudaGetSymbolAddress((void**)&off,   g_off);
    cudaGetSymbolAddress((void**)&erec,  g_erec);

    static cudaStream_t sSide = nullptr;
    static cudaEvent_t evFork = nullptr, evJoin = nullptr;
    if (sSide == nullptr) {
        cudaStreamCreateWithFlags(&sSide, cudaStreamNonBlocking);
        cudaEventCreateWithFlags(&evFork, cudaEventDisableTiming);
        cudaEventCreateWithFlags(&evJoin, cudaEventDisableTiming);
    }

    const int smem128 = 57344 + 2 * 2 * 128 * 80;   // 98304
    const int smem32  = 57344 + 2 * 2 * 32 * 80;    // 67584
    cudaFuncSetAttribute((const void*)gemm_fused<128, false>,
                         cudaFuncAttributeMaxDynamicSharedMemorySize, smem128);
    cudaFuncSetAttribute((const void*)gemm_fused<128, true>,
                         cudaFuncAttributeMaxDynamicSharedMemorySize, smem128);
    cudaFuncSetAttribute((const void*)gemm_fused<32, true>,
                         cudaFuncAttributeMaxDynamicSharedMemorySize, smem32);

    const int mTiles  = (N_NODES + 127) / 128;          // 391
    const int edgeB4  = (N_EDGES / 4 + 255) / 256;      // 782
    const int aggB128 = 148 * 8;                        // 1184
    const int aggB32  = (N_NODES * 8 + 255) / 256;      // 1563

    // ---- fork: CSR build on side stream ----
    cudaEventRecord(evFork, 0);
    cudaStreamWaitEvent(sSide, evFork, 0);
    csr_zero<<<(N_NODES + 255) / 256, 256, 0, sSide>>>(deg, stats);
    csr_hist<<<edgeB4, 256, 0, sSide>>>(dst, deg);
    csr_scan<<<1, 1024, 0, sSide>>>(deg, off, cur);
    csr_fill<<<edgeB4, 256, 0, sSide>>>(src, dst, ew, cur, erec);
    cudaEventRecord(evJoin, sSide);

    // ---- main: weights + layer-0 GEMM (reads x fp32 directly) ----
    convert_w_all<<<(288 * 256 + 255) / 256, 256>>>(W0, W1, W2, w0hi, w0lo,
                                                    w1hi, w1lo, w2hi, w2lo);
    gemm_fused<128, false><<<mTiles, 256, smem128>>>(x, w0hi, w0lo,
                                                     nullptr, nullptr, nullptr,
                                                     proj, N_NODES);

    // ---- join: aggregation needs the CSR ----
    cudaStreamWaitEvent(0, evJoin, 0);

    // ---- layer 0 -> layer 1 (BN fused into GEMM A-path) ----
    agg128_stats<<<aggB128, 256>>>(proj, off, erec, pre, stats);
    gemm_fused<128, true><<<mTiles, 256, smem128>>>(pre, w1hi, w1lo,
                                                    stats, gamma0, beta0,
                                                    proj, N_NODES);

    // ---- layer 1 -> output ----
    agg128_stats<<<aggB128, 256>>>(proj, off, erec, pre, stats + 256);
    gemm_fused<32, true><<<mTiles, 256, smem32>>>(pre, w2hi, w2lo,
                                                  stats + 256, gamma1, beta1,
                                                  proj, N_NODES);
    agg_csr32<<<aggB32, 256>>>(proj, off, erec, out);
}